// round 15
// baseline (speedup 1.0000x reference)
#include <cuda_runtime.h>

// ---------------- problem-size constants ----------------
#define NMAX 50000
#define EMAX 800000
#define F1   64
#define F2   32
#define DIN  128
#define DOUT 128
#define PAD  128          // ELL row capacity

// ---------------- device scratch ----------------
__device__ int   g_cnt[NMAX];             // zero-init at load; re-zeroed by prop_gemm3
__device__ float g_dinv[NMAX];
__device__ int   g_ell[(long long)NMAX * PAD];
__device__ float g_h1[NMAX * F1];
__device__ float g_h2[NMAX * F2];
__device__ int   g_is64;

// ---------------- f32x2 helpers ----------------
__device__ __forceinline__ void fma2(unsigned long long& d,
                                     unsigned long long a,
                                     unsigned long long b) {
    asm("fma.rn.f32x2 %0, %1, %2, %0;" : "+l"(d) : "l"(a), "l"(b));
}
__device__ __forceinline__ unsigned long long dup2(float w) {
    unsigned long long r;
    asm("mov.b64 %0, {%1, %1};" : "=l"(r) : "f"(w));
    return r;
}
__device__ __forceinline__ float lo32(unsigned long long v) {
    return __uint_as_float((unsigned)(v & 0xffffffffull));
}
__device__ __forceinline__ float hi32(unsigned long long v) {
    return __uint_as_float((unsigned)(v >> 32));
}

// ---------------- edge-index dtype detection (1 block) ----------------
__global__ void detect_kernel(const int* __restrict__ w, int E) {
    __shared__ int any_nonzero;
    if (threadIdx.x == 0) any_nonzero = 0;
    __syncthreads();
    int stride = (2 * E) / 512;
    int idx = 2 * (threadIdx.x * stride) + 1;
    if (w[idx] != 0) atomicOr(&any_nonzero, 1);
    __syncthreads();
    if (threadIdx.x == 0) g_is64 = any_nonzero ? 0 : 1;
}

// ---------------- ELL build: count + scatter in ONE pass ----------------
__global__ void scatter_count_kernel(const int* __restrict__ w, int E) {
    int e = blockIdx.x * blockDim.x + threadIdx.x;
    if (e >= E) return;
    int s, d;
    if (g_is64) { s = w[2 * e]; d = w[2 * (E + e)]; }
    else        { s = w[e];     d = w[E + e];       }
    int p = atomicAdd(&g_cnt[d], 1);
    if (p < PAD) g_ell[(long long)d * PAD + p] = s;
}

__global__ void dinv_kernel(int n) {
    int i = blockIdx.x * blockDim.x + threadIdx.x;
    if (i < n) g_dinv[i] = rsqrtf((float)(g_cnt[i] + 1));   // +1 self loop
}

// ---------------- gemm1: round-11 gemm_rt2 (TM=128, TN=64) ------------------
template<int KIN, int KOUT, int TN>
__global__ void __launch_bounds__((TN / 8) * 16)
gemm_rt2(const float* __restrict__ A, const float* __restrict__ W,
         float* __restrict__ H, int n)
{
    constexpr int TM = 128;
    constexpr int TK = 32;
    constexpr int NTX = TN / 8;
    constexpr int NTY = TM / 8;
    constexpr int NTH = NTX * NTY;
    constexpr int XPITCH = TM + 4;

    __shared__ float Xs[TK * XPITCH];
    __shared__ float Ws[TK * TN];

    const int tid = threadIdx.x;
    const int tx = tid % NTX;
    const int ty = tid / NTX;
    const int nb = blockIdx.x * TM;
    const int jn = blockIdx.y * TN;
    const int valid = min(TM, n - nb);

    unsigned long long acc[4][8];
#pragma unroll
    for (int i = 0; i < 4; i++)
#pragma unroll
        for (int j = 0; j < 8; j++) acc[i][j] = 0ull;

    for (int kt = 0; kt < KIN; kt += TK) {
#pragma unroll
        for (int idx = tid; idx < TM * TK / 4; idx += NTH) {
            int r  = idx / (TK / 4);
            int kq = idx % (TK / 4);
            float4 v = make_float4(0.f, 0.f, 0.f, 0.f);
            if (r < valid)
                v = *reinterpret_cast<const float4*>(
                        A + (long long)(nb + r) * KIN + kt + kq * 4);
            Xs[(kq * 4 + 0) * XPITCH + r] = v.x;
            Xs[(kq * 4 + 1) * XPITCH + r] = v.y;
            Xs[(kq * 4 + 2) * XPITCH + r] = v.z;
            Xs[(kq * 4 + 3) * XPITCH + r] = v.w;
        }
#pragma unroll
        for (int idx = tid; idx < TK * TN / 4; idx += NTH) {
            int kk = idx / (TN / 4);
            int jq = idx % (TN / 4);
            *reinterpret_cast<float4*>(Ws + kk * TN + jq * 4) =
                *reinterpret_cast<const float4*>(
                    W + (long long)(kt + kk) * KOUT + jn + jq * 4);
        }
        __syncthreads();

#pragma unroll
        for (int kk = 0; kk < TK; kk++) {
            const ulonglong2 pa01 = *reinterpret_cast<const ulonglong2*>(
                Xs + kk * XPITCH + ty * 8);
            const ulonglong2 pa23 = *reinterpret_cast<const ulonglong2*>(
                Xs + kk * XPITCH + ty * 8 + 4);
            const float4 b0 = *reinterpret_cast<const float4*>(Ws + kk * TN + tx * 8);
            const float4 b1 = *reinterpret_cast<const float4*>(Ws + kk * TN + tx * 8 + 4);
            unsigned long long pb[8];
            pb[0] = dup2(b0.x); pb[1] = dup2(b0.y); pb[2] = dup2(b0.z); pb[3] = dup2(b0.w);
            pb[4] = dup2(b1.x); pb[5] = dup2(b1.y); pb[6] = dup2(b1.z); pb[7] = dup2(b1.w);

            unsigned long long pa[4] = { pa01.x, pa01.y, pa23.x, pa23.y };
#pragma unroll
            for (int p = 0; p < 4; p++)
#pragma unroll
                for (int j = 0; j < 8; j++)
                    fma2(acc[p][j], pa[p], pb[j]);
        }
        __syncthreads();
    }

#pragma unroll
    for (int p = 0; p < 4; p++) {
#pragma unroll
        for (int half = 0; half < 2; half++) {
            int node = nb + ty * 8 + p * 2 + half;
            if (node < n) {
                float4 v0, v1;
                if (half == 0) {
                    v0 = make_float4(lo32(acc[p][0]), lo32(acc[p][1]),
                                     lo32(acc[p][2]), lo32(acc[p][3]));
                    v1 = make_float4(lo32(acc[p][4]), lo32(acc[p][5]),
                                     lo32(acc[p][6]), lo32(acc[p][7]));
                } else {
                    v0 = make_float4(hi32(acc[p][0]), hi32(acc[p][1]),
                                     hi32(acc[p][2]), hi32(acc[p][3]));
                    v1 = make_float4(hi32(acc[p][4]), hi32(acc[p][5]),
                                     hi32(acc[p][6]), hi32(acc[p][7]));
                }
                float* dst = H + (long long)node * KOUT + jn + tx * 8;
                *reinterpret_cast<float4*>(dst)     = v0;
                *reinterpret_cast<float4*>(dst + 4) = v1;
            }
        }
    }
}

// ---------------- fused prop64 + gemm2 --------------------------------------
// Block = 64 nodes, 128 threads. Phase 1: 4 warps gather (prop64 logic, 2
// streams x 16 lanes x float4) writing relu(prop + b1) transposed into Xs.
// Phase 2: FFMA2 GEMM (4 nodes x 4 cols per thread), KIN=64, KOUT=32.
__global__ void __launch_bounds__(128)
prop_gemm2(const float* __restrict__ h, const float* __restrict__ W,
           const float* __restrict__ ib, float* __restrict__ H, int n)
{
    constexpr int KIN = F1, KOUT = F2, TM = 64, XP = TM + 4;
    __shared__ float Xs[KIN * XP];     // 64 x 68
    __shared__ float Ws[KIN * KOUT];   // 64 x 32

    const int tid = threadIdx.x;
    const int nb = blockIdx.x * TM;

    // load W panel (512 float4 / 128 thr = 4 each)
#pragma unroll
    for (int idx = tid; idx < KIN * KOUT / 4; idx += 128)
        reinterpret_cast<float4*>(Ws)[idx] = reinterpret_cast<const float4*>(W)[idx];

    // ---- gather phase ----
    const int wpid = tid >> 5;
    const int lane = tid & 31;
    const int half = lane >> 4;
    const int fl   = lane & 15;
    const float4 bb = *reinterpret_cast<const float4*>(ib + fl * 4);

    for (int i = 0; i < 16; i++) {
        const int loc = wpid * 16 + i;
        const int v = nb + loc;
        float4 acc = make_float4(0.f, 0.f, 0.f, 0.f);
        if (v < n) {
            const int r1 = min(g_cnt[v], PAD);
            const float div = g_dinv[v];
            const int* __restrict__ row = g_ell + (long long)v * PAD;
            if (half == 0) {
                acc = *reinterpret_cast<const float4*>(h + (long long)v * KIN + fl * 4);
                acc.x *= div; acc.y *= div; acc.z *= div; acc.w *= div;
            }
            int j = half;
            for (; j + 6 < r1; j += 8) {
                int s0 = row[j], s1 = row[j + 2], s2 = row[j + 4], s3 = row[j + 6];
                float w0 = g_dinv[s0], w1 = g_dinv[s1], w2 = g_dinv[s2], w3 = g_dinv[s3];
                float4 v0 = *reinterpret_cast<const float4*>(h + (long long)s0 * KIN + fl * 4);
                float4 v1 = *reinterpret_cast<const float4*>(h + (long long)s1 * KIN + fl * 4);
                float4 v2 = *reinterpret_cast<const float4*>(h + (long long)s2 * KIN + fl * 4);
                float4 v3 = *reinterpret_cast<const float4*>(h + (long long)s3 * KIN + fl * 4);
                acc.x += w0 * v0.x; acc.y += w0 * v0.y; acc.z += w0 * v0.z; acc.w += w0 * v0.w;
                acc.x += w1 * v1.x; acc.y += w1 * v1.y; acc.z += w1 * v1.z; acc.w += w1 * v1.w;
                acc.x += w2 * v2.x; acc.y += w2 * v2.y; acc.z += w2 * v2.z; acc.w += w2 * v2.w;
                acc.x += w3 * v3.x; acc.y += w3 * v3.y; acc.z += w3 * v3.z; acc.w += w3 * v3.w;
            }
            for (; j < r1; j += 2) {
                int s = row[j];
                float w = g_dinv[s];
                float4 vv = *reinterpret_cast<const float4*>(h + (long long)s * KIN + fl * 4);
                acc.x += w * vv.x; acc.y += w * vv.y; acc.z += w * vv.z; acc.w += w * vv.w;
            }
            acc.x += __shfl_xor_sync(0xffffffffu, acc.x, 16);
            acc.y += __shfl_xor_sync(0xffffffffu, acc.y, 16);
            acc.z += __shfl_xor_sync(0xffffffffu, acc.z, 16);
            acc.w += __shfl_xor_sync(0xffffffffu, acc.w, 16);
            if (half == 0) {
                acc.x = fmaxf(acc.x * div + bb.x, 0.f);
                acc.y = fmaxf(acc.y * div + bb.y, 0.f);
                acc.z = fmaxf(acc.z * div + bb.z, 0.f);
                acc.w = fmaxf(acc.w * div + bb.w, 0.f);
            }
        }
        if (half == 0) {
            Xs[(fl * 4 + 0) * XP + loc] = acc.x;
            Xs[(fl * 4 + 1) * XP + loc] = acc.y;
            Xs[(fl * 4 + 2) * XP + loc] = acc.z;
            Xs[(fl * 4 + 3) * XP + loc] = acc.w;
        }
    }
    __syncthreads();

    // ---- GEMM phase: 4 nodes x 4 cols per thread ----
    const int tx = tid % 8;            // col group of 4 (8*4 = 32)
    const int ty = tid / 8;            // node group of 4 (16*4 = 64)

    unsigned long long acc2[2][4];
#pragma unroll
    for (int p = 0; p < 2; p++)
#pragma unroll
        for (int j = 0; j < 4; j++) acc2[p][j] = 0ull;

#pragma unroll 8
    for (int kk = 0; kk < KIN; kk++) {
        const ulonglong2 pa = *reinterpret_cast<const ulonglong2*>(Xs + kk * XP + ty * 4);
        const float4 b = *reinterpret_cast<const float4*>(Ws + kk * KOUT + tx * 4);
        unsigned long long pb[4];
        pb[0] = dup2(b.x); pb[1] = dup2(b.y); pb[2] = dup2(b.z); pb[3] = dup2(b.w);
#pragma unroll
        for (int j = 0; j < 4; j++) fma2(acc2[0][j], pa.x, pb[j]);
#pragma unroll
        for (int j = 0; j < 4; j++) fma2(acc2[1][j], pa.y, pb[j]);
    }

#pragma unroll
    for (int p = 0; p < 2; p++) {
#pragma unroll
        for (int hh = 0; hh < 2; hh++) {
            int node = nb + ty * 4 + p * 2 + hh;
            if (node < n) {
                float4 v;
                if (hh == 0)
                    v = make_float4(lo32(acc2[p][0]), lo32(acc2[p][1]),
                                    lo32(acc2[p][2]), lo32(acc2[p][3]));
                else
                    v = make_float4(hi32(acc2[p][0]), hi32(acc2[p][1]),
                                    hi32(acc2[p][2]), hi32(acc2[p][3]));
                *reinterpret_cast<float4*>(H + (long long)node * KOUT + tx * 4) = v;
            }
        }
    }
}

// ---------------- fused prop32 + gemm3 --------------------------------------
// Block = 64 nodes, 128 threads. Phase 1: 4 warps gather (prop32 logic, 4
// streams x 8 lanes x float4) writing relu(prop + b2) transposed into Xs;
// then zero g_cnt for the block's nodes. Phase 2: FFMA2 GEMM
// (8 nodes x 8 cols per thread), KIN=32, KOUT=128 (+bl).
__global__ void __launch_bounds__(128)
prop_gemm3(const float* __restrict__ h, const float* __restrict__ W,
           const float* __restrict__ ib, const float* __restrict__ ob,
           float* __restrict__ out, int n)
{
    constexpr int KIN = F2, KOUT = DOUT, TM = 64, TN = DOUT, XP = TM + 4;
    __shared__ float Xs[KIN * XP];     // 32 x 68
    __shared__ float Ws[KIN * TN];     // 32 x 128

    const int tid = threadIdx.x;
    const int nb = blockIdx.x * TM;

    // load W panel (1024 float4 / 128 thr = 8 each)
#pragma unroll
    for (int idx = tid; idx < KIN * TN / 4; idx += 128)
        reinterpret_cast<float4*>(Ws)[idx] = reinterpret_cast<const float4*>(W)[idx];

    // ---- gather phase ----
    const int wpid = tid >> 5;
    const int lane = tid & 31;
    const int q  = lane >> 3;          // stream 0..3
    const int fl = lane & 7;           // feature lane (float4)
    const float4 bb = *reinterpret_cast<const float4*>(ib + fl * 4);

    for (int i = 0; i < 16; i++) {
        const int loc = wpid * 16 + i;
        const int v = nb + loc;
        float4 acc = make_float4(0.f, 0.f, 0.f, 0.f);
        if (v < n) {
            const int r1 = min(g_cnt[v], PAD);
            const float div = g_dinv[v];
            const int* __restrict__ row = g_ell + (long long)v * PAD;
            if (q == 0) {
                acc = *reinterpret_cast<const float4*>(h + (long long)v * KIN + fl * 4);
                acc.x *= div; acc.y *= div; acc.z *= div; acc.w *= div;
            }
            int j = q;
            for (; j + 12 < r1; j += 16) {
                int s0 = row[j], s1 = row[j + 4], s2 = row[j + 8], s3 = row[j + 12];
                float w0 = g_dinv[s0], w1 = g_dinv[s1], w2 = g_dinv[s2], w3 = g_dinv[s3];
                float4 v0 = *reinterpret_cast<const float4*>(h + (long long)s0 * KIN + fl * 4);
                float4 v1 = *reinterpret_cast<const float4*>(h + (long long)s1 * KIN + fl * 4);
                float4 v2 = *reinterpret_cast<const float4*>(h + (long long)s2 * KIN + fl * 4);
                float4 v3 = *reinterpret_cast<const float4*>(h + (long long)s3 * KIN + fl * 4);
                acc.x += w0 * v0.x; acc.y += w0 * v0.y; acc.z += w0 * v0.z; acc.w += w0 * v0.w;
                acc.x += w1 * v1.x; acc.y += w1 * v1.y; acc.z += w1 * v1.z; acc.w += w1 * v1.w;
                acc.x += w2 * v2.x; acc.y += w2 * v2.y; acc.z += w2 * v2.z; acc.w += w2 * v2.w;
                acc.x += w3 * v3.x; acc.y += w3 * v3.y; acc.z += w3 * v3.z; acc.w += w3 * v3.w;
            }
            for (; j < r1; j += 4) {
                int s = row[j];
                float w = g_dinv[s];
                float4 vv = *reinterpret_cast<const float4*>(h + (long long)s * KIN + fl * 4);
                acc.x += w * vv.x; acc.y += w * vv.y; acc.z += w * vv.z; acc.w += w * vv.w;
            }
#pragma unroll
            for (int o = 8; o <= 16; o <<= 1) {
                acc.x += __shfl_xor_sync(0xffffffffu, acc.x, o);
                acc.y += __shfl_xor_sync(0xffffffffu, acc.y, o);
                acc.z += __shfl_xor_sync(0xffffffffu, acc.z, o);
                acc.w += __shfl_xor_sync(0xffffffffu, acc.w, o);
            }
            if (q == 0) {
                acc.x = fmaxf(acc.x * div + bb.x, 0.f);
                acc.y = fmaxf(acc.y * div + bb.y, 0.f);
                acc.z = fmaxf(acc.z * div + bb.z, 0.f);
                acc.w = fmaxf(acc.w * div + bb.w, 0.f);
            }
        }
        if (q == 0) {
            Xs[(fl * 4 + 0) * XP + loc] = acc.x;
            Xs[(fl * 4 + 1) * XP + loc] = acc.y;
            Xs[(fl * 4 + 2) * XP + loc] = acc.z;
            Xs[(fl * 4 + 3) * XP + loc] = acc.w;
        }
    }
    __syncthreads();

    // re-zero g_cnt for this block's nodes (all gather reads are done)
    if (tid < TM && nb + tid < n) g_cnt[nb + tid] = 0;

    // ---- GEMM phase: 8 nodes x 8 cols per thread ----
    const int tx = tid % 16;           // col group of 8 (16*8 = 128)
    const int ty = tid / 16;           // node group of 8 (8*8 = 64)

    unsigned long long acc2[4][8];
#pragma unroll
    for (int p = 0; p < 4; p++)
#pragma unroll
        for (int j = 0; j < 8; j++) acc2[p][j] = 0ull;

#pragma unroll 4
    for (int kk = 0; kk < KIN; kk++) {
        const ulonglong2 pa01 = *reinterpret_cast<const ulonglong2*>(Xs + kk * XP + ty * 8);
        const ulonglong2 pa23 = *reinterpret_cast<const ulonglong2*>(Xs + kk * XP + ty * 8 + 4);
        const float4 b0 = *reinterpret_cast<const float4*>(Ws + kk * TN + tx * 8);
        const float4 b1 = *reinterpret_cast<const float4*>(Ws + kk * TN + tx * 8 + 4);
        unsigned long long pb[8];
        pb[0] = dup2(b0.x); pb[1] = dup2(b0.y); pb[2] = dup2(b0.z); pb[3] = dup2(b0.w);
        pb[4] = dup2(b1.x); pb[5] = dup2(b1.y); pb[6] = dup2(b1.z); pb[7] = dup2(b1.w);

        unsigned long long pa[4] = { pa01.x, pa01.y, pa23.x, pa23.y };
#pragma unroll
        for (int p = 0; p < 4; p++)
#pragma unroll
            for (int j = 0; j < 8; j++)
                fma2(acc2[p][j], pa[p], pb[j]);
    }

    const float4 bo0 = *reinterpret_cast<const float4*>(ob + tx * 8);
    const float4 bo1 = *reinterpret_cast<const float4*>(ob + tx * 8 + 4);
#pragma unroll
    for (int p = 0; p < 4; p++) {
#pragma unroll
        for (int hh = 0; hh < 2; hh++) {
            int node = nb + ty * 8 + p * 2 + hh;
            if (node < n) {
                float4 v0, v1;
                if (hh == 0) {
                    v0 = make_float4(lo32(acc2[p][0]), lo32(acc2[p][1]),
                                     lo32(acc2[p][2]), lo32(acc2[p][3]));
                    v1 = make_float4(lo32(acc2[p][4]), lo32(acc2[p][5]),
                                     lo32(acc2[p][6]), lo32(acc2[p][7]));
                } else {
                    v0 = make_float4(hi32(acc2[p][0]), hi32(acc2[p][1]),
                                     hi32(acc2[p][2]), hi32(acc2[p][3]));
                    v1 = make_float4(hi32(acc2[p][4]), hi32(acc2[p][5]),
                                     hi32(acc2[p][6]), hi32(acc2[p][7]));
                }
                v0.x += bo0.x; v0.y += bo0.y; v0.z += bo0.z; v0.w += bo0.w;
                v1.x += bo1.x; v1.y += bo1.y; v1.z += bo1.z; v1.w += bo1.w;
                float* dst = out + (long long)node * KOUT + tx * 8;
                *reinterpret_cast<float4*>(dst)     = v0;
                *reinterpret_cast<float4*>(dst + 4) = v1;
            }
        }
    }
}

// ---------------- launcher (forked-stream, fused pipeline) ------------------
extern "C" void kernel_launch(void* const* d_in, const int* in_sizes, int n_in,
                              void* d_out, int out_size)
{
    const float* x  = (const float*)d_in[0];
    const int*   ei = (const int*)  d_in[1];
    const float* W1 = (const float*)d_in[2];
    const float* b1 = (const float*)d_in[3];
    const float* W2 = (const float*)d_in[4];
    const float* b2 = (const float*)d_in[5];
    const float* Wl = (const float*)d_in[6];
    const float* bl = (const float*)d_in[7];
    float* out = (float*)d_out;

    const int n = in_sizes[0] / DIN;
    const int E = in_sizes[1] / 2;

    void *ph1, *ph2;
    cudaGetSymbolAddress(&ph1, g_h1);
    cudaGetSymbolAddress(&ph2, g_h2);
    float* h1 = (float*)ph1;
    float* h2 = (float*)ph2;

    const int nblk128 = (n + 127) / 128;
    const int nblk64  = (n + 63) / 64;

    cudaStream_t s2;
    cudaStreamCreateWithFlags(&s2, cudaStreamNonBlocking);
    cudaEvent_t evFork, evJoin;
    cudaEventCreateWithFlags(&evFork, cudaEventDisableTiming);
    cudaEventCreateWithFlags(&evJoin, cudaEventDisableTiming);

    // fork: ELL build on s2, concurrent with gemm1 on the main stream
    cudaEventRecord(evFork, 0);
    cudaStreamWaitEvent(s2, evFork, 0);

    detect_kernel<<<1, 256, 0, s2>>>(ei, E);
    scatter_count_kernel<<<(E + 255) / 256, 256, 0, s2>>>(ei, E);
    dinv_kernel<<<(n + 255) / 256, 256, 0, s2>>>(n);
    cudaEventRecord(evJoin, s2);

    // main stream: layer-1 GEMM overlaps ELL build
    gemm_rt2<DIN, F1, 64><<<dim3(nblk128, 1), 128>>>(x, W1, h1, n);

    cudaStreamWaitEvent(0, evJoin, 0);

    // fused layer-2: h2 = relu(prop(h1) + b1) @ W2
    prop_gemm2<<<nblk64, 128>>>(h1, W2, b1, h2, n);
    // fused head: out = relu(prop(h2) + b2) @ Wl + bl  (also re-zeros g_cnt)
    prop_gemm3<<<nblk64, 128>>>(h2, Wl, b2, bl, out, n);

    cudaEventDestroy(evFork);
    cudaEventDestroy(evJoin);
    cudaStreamDestroy(s2);
}

// round 16
// speedup vs baseline: 1.1667x; 1.1667x over previous
#include <cuda_runtime.h>

// ---------------- problem-size constants ----------------
#define NMAX 50000
#define EMAX 800000
#define F1   64
#define F2   32
#define DIN  128
#define DOUT 128
#define PAD  128          // ELL row capacity

// ---------------- device scratch ----------------
__device__ int   g_cnt[NMAX];             // zero-init at load; re-zeroed by gemm3
__device__ float g_dinv[NMAX];
__device__ int   g_ell[(long long)NMAX * PAD];
__device__ float g_h1[NMAX * F1];
__device__ float g_a1[NMAX * F1];
__device__ float g_h2[NMAX * F2];
__device__ float g_a2[NMAX * F2];
__device__ int   g_is64;

// ---------------- f32x2 helpers ----------------
__device__ __forceinline__ void fma2(unsigned long long& d,
                                     unsigned long long a,
                                     unsigned long long b) {
    asm("fma.rn.f32x2 %0, %1, %2, %0;" : "+l"(d) : "l"(a), "l"(b));
}
__device__ __forceinline__ unsigned long long dup2(float w) {
    unsigned long long r;
    asm("mov.b64 %0, {%1, %1};" : "=l"(r) : "f"(w));
    return r;
}
__device__ __forceinline__ float lo32(unsigned long long v) {
    return __uint_as_float((unsigned)(v & 0xffffffffull));
}
__device__ __forceinline__ float hi32(unsigned long long v) {
    return __uint_as_float((unsigned)(v >> 32));
}

// ---------------- edge-index dtype detection (1 block) ----------------
__global__ void detect_kernel(const int* __restrict__ w, int E) {
    __shared__ int any_nonzero;
    if (threadIdx.x == 0) any_nonzero = 0;
    __syncthreads();
    int stride = (2 * E) / 512;
    int idx = 2 * (threadIdx.x * stride) + 1;
    if (w[idx] != 0) atomicOr(&any_nonzero, 1);
    __syncthreads();
    if (threadIdx.x == 0) g_is64 = any_nonzero ? 0 : 1;
}

// ---------------- ELL build: count + scatter in ONE pass ----------------
__global__ void scatter_count_kernel(const int* __restrict__ w, int E) {
    int e = blockIdx.x * blockDim.x + threadIdx.x;
    if (e >= E) return;
    int s, d;
    if (g_is64) { s = w[2 * e]; d = w[2 * (E + e)]; }
    else        { s = w[e];     d = w[E + e];       }
    int p = atomicAdd(&g_cnt[d], 1);
    if (p < PAD) g_ell[(long long)d * PAD + p] = s;
}

__global__ void dinv_kernel(int n) {
    int i = blockIdx.x * blockDim.x + threadIdx.x;
    if (i < n) g_dinv[i] = rsqrtf((float)(g_cnt[i] + 1));   // +1 self loop
}

// ---------------- f32x2 GEMM: 8 nodes x 8 cols per thread (round-11) --------
// MINB: min blocks/SM hint — caps regs to raise occupancy (latency cover).
template<int KIN, int KOUT, int TN, bool INACT, bool OBIAS, bool ZCNT, int MINB>
__global__ void __launch_bounds__((TN / 8) * 16, MINB)
gemm_rt2(const float* __restrict__ A, const float* __restrict__ W,
         const float* __restrict__ ib, const float* __restrict__ ob,
         float* __restrict__ H, int n)
{
    constexpr int TM = 128;
    constexpr int TK = (KIN < 32) ? KIN : 32;
    constexpr int NTX = TN / 8;
    constexpr int NTY = TM / 8;
    constexpr int NTH = NTX * NTY;
    constexpr int XPITCH = TM + 4;

    __shared__ float Xs[TK * XPITCH];
    __shared__ float Ws[TK * TN];

    const int tid = threadIdx.x;
    const int tx = tid % NTX;
    const int ty = tid / NTX;
    const int nb = blockIdx.x * TM;
    const int jn = blockIdx.y * TN;
    const int valid = min(TM, n - nb);

    if (ZCNT && blockIdx.y == 0 && tid < TM) {
        int idx = nb + tid;
        if (idx < n) g_cnt[idx] = 0;
    }

    unsigned long long acc[4][8];
#pragma unroll
    for (int i = 0; i < 4; i++)
#pragma unroll
        for (int j = 0; j < 8; j++) acc[i][j] = 0ull;

    for (int kt = 0; kt < KIN; kt += TK) {
#pragma unroll
        for (int idx = tid; idx < TM * TK / 4; idx += NTH) {
            int r  = idx / (TK / 4);
            int kq = idx % (TK / 4);
            float4 v = make_float4(0.f, 0.f, 0.f, 0.f);
            if (r < valid)
                v = *reinterpret_cast<const float4*>(
                        A + (long long)(nb + r) * KIN + kt + kq * 4);
            if (INACT) {
                const float4 bb = *reinterpret_cast<const float4*>(ib + kt + kq * 4);
                v.x = fmaxf(v.x + bb.x, 0.f);
                v.y = fmaxf(v.y + bb.y, 0.f);
                v.z = fmaxf(v.z + bb.z, 0.f);
                v.w = fmaxf(v.w + bb.w, 0.f);
            }
            Xs[(kq * 4 + 0) * XPITCH + r] = v.x;
            Xs[(kq * 4 + 1) * XPITCH + r] = v.y;
            Xs[(kq * 4 + 2) * XPITCH + r] = v.z;
            Xs[(kq * 4 + 3) * XPITCH + r] = v.w;
        }
#pragma unroll
        for (int idx = tid; idx < TK * TN / 4; idx += NTH) {
            int kk = idx / (TN / 4);
            int jq = idx % (TN / 4);
            *reinterpret_cast<float4*>(Ws + kk * TN + jq * 4) =
                *reinterpret_cast<const float4*>(
                    W + (long long)(kt + kk) * KOUT + jn + jq * 4);
        }
        __syncthreads();

#pragma unroll
        for (int kk = 0; kk < TK; kk++) {
            const ulonglong2 pa01 = *reinterpret_cast<const ulonglong2*>(
                Xs + kk * XPITCH + ty * 8);
            const ulonglong2 pa23 = *reinterpret_cast<const ulonglong2*>(
                Xs + kk * XPITCH + ty * 8 + 4);
            const float4 b0 = *reinterpret_cast<const float4*>(Ws + kk * TN + tx * 8);
            const float4 b1 = *reinterpret_cast<const float4*>(Ws + kk * TN + tx * 8 + 4);
            unsigned long long pb[8];
            pb[0] = dup2(b0.x); pb[1] = dup2(b0.y); pb[2] = dup2(b0.z); pb[3] = dup2(b0.w);
            pb[4] = dup2(b1.x); pb[5] = dup2(b1.y); pb[6] = dup2(b1.z); pb[7] = dup2(b1.w);

            unsigned long long pa[4] = { pa01.x, pa01.y, pa23.x, pa23.y };
#pragma unroll
            for (int p = 0; p < 4; p++)
#pragma unroll
                for (int j = 0; j < 8; j++)
                    fma2(acc[p][j], pa[p], pb[j]);
        }
        __syncthreads();
    }

    float4 bo0 = make_float4(0.f, 0.f, 0.f, 0.f);
    float4 bo1 = make_float4(0.f, 0.f, 0.f, 0.f);
    if (OBIAS) {
        bo0 = *reinterpret_cast<const float4*>(ob + jn + tx * 8);
        bo1 = *reinterpret_cast<const float4*>(ob + jn + tx * 8 + 4);
    }
#pragma unroll
    for (int p = 0; p < 4; p++) {
#pragma unroll
        for (int half = 0; half < 2; half++) {
            int node = nb + ty * 8 + p * 2 + half;
            if (node < n) {
                float4 v0, v1;
                if (half == 0) {
                    v0 = make_float4(lo32(acc[p][0]), lo32(acc[p][1]),
                                     lo32(acc[p][2]), lo32(acc[p][3]));
                    v1 = make_float4(lo32(acc[p][4]), lo32(acc[p][5]),
                                     lo32(acc[p][6]), lo32(acc[p][7]));
                } else {
                    v0 = make_float4(hi32(acc[p][0]), hi32(acc[p][1]),
                                     hi32(acc[p][2]), hi32(acc[p][3]));
                    v1 = make_float4(hi32(acc[p][4]), hi32(acc[p][5]),
                                     hi32(acc[p][6]), hi32(acc[p][7]));
                }
                v0.x += bo0.x; v0.y += bo0.y; v0.z += bo0.z; v0.w += bo0.w;
                v1.x += bo1.x; v1.y += bo1.y; v1.z += bo1.z; v1.w += bo1.w;
                float* dst = H + (long long)node * KOUT + jn + tx * 8;
                *reinterpret_cast<float4*>(dst)     = v0;
                *reinterpret_cast<float4*>(dst + 4) = v1;
            }
        }
    }
}

// ---------------- ELL gather propagation: multi-stream warps (round-11) -----
__global__ void __launch_bounds__(256)
prop64_kernel(const float* __restrict__ h, float* __restrict__ g, int n)
{
    const int v = (blockIdx.x * blockDim.x + threadIdx.x) >> 5;
    if (v >= n) return;
    const int lane = threadIdx.x & 31;
    const int half = lane >> 4;
    const int fl   = lane & 15;
    const int r1 = min(g_cnt[v], PAD);
    const float div = g_dinv[v];
    const int* __restrict__ row = g_ell + (long long)v * PAD;

    float4 acc = make_float4(0.f, 0.f, 0.f, 0.f);
    if (half == 0) {
        acc = *reinterpret_cast<const float4*>(h + (long long)v * F1 + fl * 4);
        acc.x *= div; acc.y *= div; acc.z *= div; acc.w *= div;
    }

    int j = half;
    for (; j + 6 < r1; j += 8) {
        int s0 = row[j], s1 = row[j + 2], s2 = row[j + 4], s3 = row[j + 6];
        float w0 = g_dinv[s0], w1 = g_dinv[s1], w2 = g_dinv[s2], w3 = g_dinv[s3];
        float4 v0 = *reinterpret_cast<const float4*>(h + (long long)s0 * F1 + fl * 4);
        float4 v1 = *reinterpret_cast<const float4*>(h + (long long)s1 * F1 + fl * 4);
        float4 v2 = *reinterpret_cast<const float4*>(h + (long long)s2 * F1 + fl * 4);
        float4 v3 = *reinterpret_cast<const float4*>(h + (long long)s3 * F1 + fl * 4);
        acc.x += w0 * v0.x; acc.y += w0 * v0.y; acc.z += w0 * v0.z; acc.w += w0 * v0.w;
        acc.x += w1 * v1.x; acc.y += w1 * v1.y; acc.z += w1 * v1.z; acc.w += w1 * v1.w;
        acc.x += w2 * v2.x; acc.y += w2 * v2.y; acc.z += w2 * v2.z; acc.w += w2 * v2.w;
        acc.x += w3 * v3.x; acc.y += w3 * v3.y; acc.z += w3 * v3.z; acc.w += w3 * v3.w;
    }
    for (; j < r1; j += 2) {
        int s = row[j];
        float w = g_dinv[s];
        float4 vv = *reinterpret_cast<const float4*>(h + (long long)s * F1 + fl * 4);
        acc.x += w * vv.x; acc.y += w * vv.y; acc.z += w * vv.z; acc.w += w * vv.w;
    }

    acc.x += __shfl_xor_sync(0xffffffffu, acc.x, 16);
    acc.y += __shfl_xor_sync(0xffffffffu, acc.y, 16);
    acc.z += __shfl_xor_sync(0xffffffffu, acc.z, 16);
    acc.w += __shfl_xor_sync(0xffffffffu, acc.w, 16);
    if (half == 0) {
        acc.x *= div; acc.y *= div; acc.z *= div; acc.w *= div;
        *reinterpret_cast<float4*>(g + (long long)v * F1 + fl * 4) = acc;
    }
}

__global__ void __launch_bounds__(256)
prop32_kernel(const float* __restrict__ h, float* __restrict__ g, int n)
{
    const int v = (blockIdx.x * blockDim.x + threadIdx.x) >> 5;
    if (v >= n) return;
    const int lane = threadIdx.x & 31;
    const int q  = lane >> 3;
    const int fl = lane & 7;
    const int r1 = min(g_cnt[v], PAD);
    const float div = g_dinv[v];
    const int* __restrict__ row = g_ell + (long long)v * PAD;

    float4 acc = make_float4(0.f, 0.f, 0.f, 0.f);
    if (q == 0) {
        acc = *reinterpret_cast<const float4*>(h + (long long)v * F2 + fl * 4);
        acc.x *= div; acc.y *= div; acc.z *= div; acc.w *= div;
    }

    int j = q;
    for (; j + 12 < r1; j += 16) {
        int s0 = row[j], s1 = row[j + 4], s2 = row[j + 8], s3 = row[j + 12];
        float w0 = g_dinv[s0], w1 = g_dinv[s1], w2 = g_dinv[s2], w3 = g_dinv[s3];
        float4 v0 = *reinterpret_cast<const float4*>(h + (long long)s0 * F2 + fl * 4);
        float4 v1 = *reinterpret_cast<const float4*>(h + (long long)s1 * F2 + fl * 4);
        float4 v2 = *reinterpret_cast<const float4*>(h + (long long)s2 * F2 + fl * 4);
        float4 v3 = *reinterpret_cast<const float4*>(h + (long long)s3 * F2 + fl * 4);
        acc.x += w0 * v0.x; acc.y += w0 * v0.y; acc.z += w0 * v0.z; acc.w += w0 * v0.w;
        acc.x += w1 * v1.x; acc.y += w1 * v1.y; acc.z += w1 * v1.z; acc.w += w1 * v1.w;
        acc.x += w2 * v2.x; acc.y += w2 * v2.y; acc.z += w2 * v2.z; acc.w += w2 * v2.w;
        acc.x += w3 * v3.x; acc.y += w3 * v3.y; acc.z += w3 * v3.z; acc.w += w3 * v3.w;
    }
    for (; j < r1; j += 4) {
        int s = row[j];
        float w = g_dinv[s];
        float4 vv = *reinterpret_cast<const float4*>(h + (long long)s * F2 + fl * 4);
        acc.x += w * vv.x; acc.y += w * vv.y; acc.z += w * vv.z; acc.w += w * vv.w;
    }

#pragma unroll
    for (int o = 8; o <= 16; o <<= 1) {
        acc.x += __shfl_xor_sync(0xffffffffu, acc.x, o);
        acc.y += __shfl_xor_sync(0xffffffffu, acc.y, o);
        acc.z += __shfl_xor_sync(0xffffffffu, acc.z, o);
        acc.w += __shfl_xor_sync(0xffffffffu, acc.w, o);
    }
    if (q == 0) {
        acc.x *= div; acc.y *= div; acc.z *= div; acc.w *= div;
        *reinterpret_cast<float4*>(g + (long long)v * F2 + fl * 4) = acc;
    }
}

// ---------------- launcher (round-11 forked-stream structure) ---------------
extern "C" void kernel_launch(void* const* d_in, const int* in_sizes, int n_in,
                              void* d_out, int out_size)
{
    const float* x  = (const float*)d_in[0];
    const int*   ei = (const int*)  d_in[1];
    const float* W1 = (const float*)d_in[2];
    const float* b1 = (const float*)d_in[3];
    const float* W2 = (const float*)d_in[4];
    const float* b2 = (const float*)d_in[5];
    const float* Wl = (const float*)d_in[6];
    const float* bl = (const float*)d_in[7];
    float* out = (float*)d_out;

    const int n = in_sizes[0] / DIN;
    const int E = in_sizes[1] / 2;

    void *ph1, *pa1, *ph2, *pa2;
    cudaGetSymbolAddress(&ph1, g_h1);
    cudaGetSymbolAddress(&pa1, g_a1);
    cudaGetSymbolAddress(&ph2, g_h2);
    cudaGetSymbolAddress(&pa2, g_a2);
    float* h1 = (float*)ph1; float* a1 = (float*)pa1;
    float* h2 = (float*)ph2; float* a2 = (float*)pa2;

    const int nblk = (n + 127) / 128;    // TM=128
    const int pblk = (n * 32 + 255) / 256;

    cudaStream_t s2;
    cudaStreamCreateWithFlags(&s2, cudaStreamNonBlocking);
    cudaEvent_t evFork, evJoin;
    cudaEventCreateWithFlags(&evFork, cudaEventDisableTiming);
    cudaEventCreateWithFlags(&evJoin, cudaEventDisableTiming);

    // fork: ELL build on s2, concurrent with gemm1 on the main stream
    cudaEventRecord(evFork, 0);
    cudaStreamWaitEvent(s2, evFork, 0);

    detect_kernel<<<1, 256, 0, s2>>>(ei, E);
    scatter_count_kernel<<<(E + 255) / 256, 256, 0, s2>>>(ei, E);
    dinv_kernel<<<(n + 255) / 256, 256, 0, s2>>>(n);
    cudaEventRecord(evJoin, s2);

    // main stream: layer-1 GEMM overlaps ELL build (4 blocks/SM hint)
    gemm_rt2<DIN, F1, 64, false, false, false, 4>
        <<<dim3(nblk, 1), 128>>>(x, W1, nullptr, nullptr, h1, n);

    cudaStreamWaitEvent(0, evJoin, 0);

    prop64_kernel<<<pblk, 256>>>(h1, a1, n);
    gemm_rt2<F1, F2, 32, true, false, false, 4>
        <<<dim3(nblk, 1), 64>>>(a1, W2, b1, nullptr, h2, n);
    prop32_kernel<<<pblk, 256>>>(h2, a2, n);
    // gemm3 also re-zeroes g_cnt for the next replay (ZCNT=true)
    gemm_rt2<F2, DOUT, 64, true, true, true, 4>
        <<<dim3(nblk, 2), 128>>>(a2, Wl, b2, bl, out, n);

    cudaEventDestroy(evFork);
    cudaEventDestroy(evJoin);
    cudaStreamDestroy(s2);
}

// round 17
// speedup vs baseline: 1.2374x; 1.0606x over previous
#include <cuda_runtime.h>

// ---------------- problem-size constants ----------------
#define NMAX 50000
#define EMAX 800000
#define F1   64
#define F2   32
#define DIN  128
#define DOUT 128
#define PAD  128          // ELL row capacity

// ---------------- device scratch ----------------
__device__ int   g_cnt[NMAX];             // zero-init at load; re-zeroed by gemm3
__device__ float g_dinv[NMAX];
__device__ int   g_ell[(long long)NMAX * PAD];
__device__ float g_h1[NMAX * F1];
__device__ float g_a1[NMAX * F1];
__device__ float g_h2[NMAX * F2];
__device__ float g_a2[NMAX * F2];
__device__ int   g_is64;

// ---------------- f32x2 helpers ----------------
__device__ __forceinline__ void fma2(unsigned long long& d,
                                     unsigned long long a,
                                     unsigned long long b) {
    asm("fma.rn.f32x2 %0, %1, %2, %0;" : "+l"(d) : "l"(a), "l"(b));
}
__device__ __forceinline__ unsigned long long dup2(float w) {
    unsigned long long r;
    asm("mov.b64 %0, {%1, %1};" : "=l"(r) : "f"(w));
    return r;
}
__device__ __forceinline__ float lo32(unsigned long long v) {
    return __uint_as_float((unsigned)(v & 0xffffffffull));
}
__device__ __forceinline__ float hi32(unsigned long long v) {
    return __uint_as_float((unsigned)(v >> 32));
}

// ---------------- edge-index dtype detection (1 block) ----------------
__global__ void detect_kernel(const int* __restrict__ w, int E) {
    __shared__ int any_nonzero;
    if (threadIdx.x == 0) any_nonzero = 0;
    __syncthreads();
    int stride = (2 * E) / 512;
    int idx = 2 * (threadIdx.x * stride) + 1;
    if (w[idx] != 0) atomicOr(&any_nonzero, 1);
    __syncthreads();
    if (threadIdx.x == 0) g_is64 = any_nonzero ? 0 : 1;
}

// ---------------- ELL build: count + scatter in ONE pass ----------------
__global__ void scatter_count_kernel(const int* __restrict__ w, int E) {
    int e = blockIdx.x * blockDim.x + threadIdx.x;
    if (e >= E) return;
    int s, d;
    if (g_is64) { s = w[2 * e]; d = w[2 * (E + e)]; }
    else        { s = w[e];     d = w[E + e];       }
    int p = atomicAdd(&g_cnt[d], 1);
    if (p < PAD) g_ell[(long long)d * PAD + p] = s;
}

__global__ void dinv_kernel(int n) {
    int i = blockIdx.x * blockDim.x + threadIdx.x;
    if (i < n) g_dinv[i] = rsqrtf((float)(g_cnt[i] + 1));   // +1 self loop
}

// ---------------- f32x2 GEMM: 8 nodes x 8 cols per thread (round-11) --------
template<int KIN, int KOUT, int TN, bool INACT, bool OBIAS, bool ZCNT>
__global__ void __launch_bounds__((TN / 8) * 16)
gemm_rt2(const float* __restrict__ A, const float* __restrict__ W,
         const float* __restrict__ ib, const float* __restrict__ ob,
         float* __restrict__ H, int n)
{
    constexpr int TM = 128;
    constexpr int TK = (KIN < 32) ? KIN : 32;
    constexpr int NTX = TN / 8;
    constexpr int NTY = TM / 8;
    constexpr int NTH = NTX * NTY;
    constexpr int XPITCH = TM + 4;

    __shared__ float Xs[TK * XPITCH];
    __shared__ float Ws[TK * TN];

    const int tid = threadIdx.x;
    const int tx = tid % NTX;
    const int ty = tid / NTX;
    const int nb = blockIdx.x * TM;
    const int jn = blockIdx.y * TN;
    const int valid = min(TM, n - nb);

    if (ZCNT && blockIdx.y == 0 && tid < TM) {
        int idx = nb + tid;
        if (idx < n) g_cnt[idx] = 0;
    }

    unsigned long long acc[4][8];
#pragma unroll
    for (int i = 0; i < 4; i++)
#pragma unroll
        for (int j = 0; j < 8; j++) acc[i][j] = 0ull;

    for (int kt = 0; kt < KIN; kt += TK) {
#pragma unroll
        for (int idx = tid; idx < TM * TK / 4; idx += NTH) {
            int r  = idx / (TK / 4);
            int kq = idx % (TK / 4);
            float4 v = make_float4(0.f, 0.f, 0.f, 0.f);
            if (r < valid)
                v = *reinterpret_cast<const float4*>(
                        A + (long long)(nb + r) * KIN + kt + kq * 4);
            if (INACT) {
                const float4 bb = *reinterpret_cast<const float4*>(ib + kt + kq * 4);
                v.x = fmaxf(v.x + bb.x, 0.f);
                v.y = fmaxf(v.y + bb.y, 0.f);
                v.z = fmaxf(v.z + bb.z, 0.f);
                v.w = fmaxf(v.w + bb.w, 0.f);
            }
            Xs[(kq * 4 + 0) * XPITCH + r] = v.x;
            Xs[(kq * 4 + 1) * XPITCH + r] = v.y;
            Xs[(kq * 4 + 2) * XPITCH + r] = v.z;
            Xs[(kq * 4 + 3) * XPITCH + r] = v.w;
        }
#pragma unroll
        for (int idx = tid; idx < TK * TN / 4; idx += NTH) {
            int kk = idx / (TN / 4);
            int jq = idx % (TN / 4);
            *reinterpret_cast<float4*>(Ws + kk * TN + jq * 4) =
                *reinterpret_cast<const float4*>(
                    W + (long long)(kt + kk) * KOUT + jn + jq * 4);
        }
        __syncthreads();

#pragma unroll
        for (int kk = 0; kk < TK; kk++) {
            const ulonglong2 pa01 = *reinterpret_cast<const ulonglong2*>(
                Xs + kk * XPITCH + ty * 8);
            const ulonglong2 pa23 = *reinterpret_cast<const ulonglong2*>(
                Xs + kk * XPITCH + ty * 8 + 4);
            const float4 b0 = *reinterpret_cast<const float4*>(Ws + kk * TN + tx * 8);
            const float4 b1 = *reinterpret_cast<const float4*>(Ws + kk * TN + tx * 8 + 4);
            unsigned long long pb[8];
            pb[0] = dup2(b0.x); pb[1] = dup2(b0.y); pb[2] = dup2(b0.z); pb[3] = dup2(b0.w);
            pb[4] = dup2(b1.x); pb[5] = dup2(b1.y); pb[6] = dup2(b1.z); pb[7] = dup2(b1.w);

            unsigned long long pa[4] = { pa01.x, pa01.y, pa23.x, pa23.y };
#pragma unroll
            for (int p = 0; p < 4; p++)
#pragma unroll
                for (int j = 0; j < 8; j++)
                    fma2(acc[p][j], pa[p], pb[j]);
        }
        __syncthreads();
    }

    float4 bo0 = make_float4(0.f, 0.f, 0.f, 0.f);
    float4 bo1 = make_float4(0.f, 0.f, 0.f, 0.f);
    if (OBIAS) {
        bo0 = *reinterpret_cast<const float4*>(ob + jn + tx * 8);
        bo1 = *reinterpret_cast<const float4*>(ob + jn + tx * 8 + 4);
    }
#pragma unroll
    for (int p = 0; p < 4; p++) {
#pragma unroll
        for (int half = 0; half < 2; half++) {
            int node = nb + ty * 8 + p * 2 + half;
            if (node < n) {
                float4 v0, v1;
                if (half == 0) {
                    v0 = make_float4(lo32(acc[p][0]), lo32(acc[p][1]),
                                     lo32(acc[p][2]), lo32(acc[p][3]));
                    v1 = make_float4(lo32(acc[p][4]), lo32(acc[p][5]),
                                     lo32(acc[p][6]), lo32(acc[p][7]));
                } else {
                    v0 = make_float4(hi32(acc[p][0]), hi32(acc[p][1]),
                                     hi32(acc[p][2]), hi32(acc[p][3]));
                    v1 = make_float4(hi32(acc[p][4]), hi32(acc[p][5]),
                                     hi32(acc[p][6]), hi32(acc[p][7]));
                }
                v0.x += bo0.x; v0.y += bo0.y; v0.z += bo0.z; v0.w += bo0.w;
                v1.x += bo1.x; v1.y += bo1.y; v1.z += bo1.z; v1.w += bo1.w;
                float* dst = H + (long long)node * KOUT + jn + tx * 8;
                *reinterpret_cast<float4*>(dst)     = v0;
                *reinterpret_cast<float4*>(dst + 4) = v1;
            }
        }
    }
}

// ---------------- prop64: 4 groups = (edge-parity x feature-half) -----------
// Each group: 8 lanes x float4 covering 32 of 64 features, stride-2 edge
// slice, 4-edge unroll -> 16 independent LDG.128 in flight per warp.
// shfl_xor(8) combines edge parities; groups q0/q2 store the two halves.
__global__ void __launch_bounds__(256)
prop64_kernel(const float* __restrict__ h, float* __restrict__ g, int n)
{
    const int v = (blockIdx.x * blockDim.x + threadIdx.x) >> 5;
    if (v >= n) return;
    const int lane = threadIdx.x & 31;
    const int q     = lane >> 3;         // group 0..3
    const int fl    = lane & 7;          // float4 lane within half
    const int e_par = q & 1;             // edge-slice parity
    const int fh    = q >> 1;            // feature half (0: 0..31, 1: 32..63)
    const int foff  = fh * 32 + fl * 4;  // feature offset
    const int r1 = min(g_cnt[v], PAD);
    const float div = g_dinv[v];
    const int* __restrict__ row = g_ell + (long long)v * PAD;

    float4 acc = make_float4(0.f, 0.f, 0.f, 0.f);
    if (e_par == 0) {
        acc = *reinterpret_cast<const float4*>(h + (long long)v * F1 + foff);
        acc.x *= div; acc.y *= div; acc.z *= div; acc.w *= div;
    }

    int j = e_par;
    for (; j + 6 < r1; j += 8) {          // 4 edges per group per iter
        int s0 = row[j], s1 = row[j + 2], s2 = row[j + 4], s3 = row[j + 6];
        float w0 = g_dinv[s0], w1 = g_dinv[s1], w2 = g_dinv[s2], w3 = g_dinv[s3];
        float4 v0 = *reinterpret_cast<const float4*>(h + (long long)s0 * F1 + foff);
        float4 v1 = *reinterpret_cast<const float4*>(h + (long long)s1 * F1 + foff);
        float4 v2 = *reinterpret_cast<const float4*>(h + (long long)s2 * F1 + foff);
        float4 v3 = *reinterpret_cast<const float4*>(h + (long long)s3 * F1 + foff);
        acc.x += w0 * v0.x; acc.y += w0 * v0.y; acc.z += w0 * v0.z; acc.w += w0 * v0.w;
        acc.x += w1 * v1.x; acc.y += w1 * v1.y; acc.z += w1 * v1.z; acc.w += w1 * v1.w;
        acc.x += w2 * v2.x; acc.y += w2 * v2.y; acc.z += w2 * v2.z; acc.w += w2 * v2.w;
        acc.x += w3 * v3.x; acc.y += w3 * v3.y; acc.z += w3 * v3.z; acc.w += w3 * v3.w;
    }
    for (; j < r1; j += 2) {
        int s = row[j];
        float w = g_dinv[s];
        float4 vv = *reinterpret_cast<const float4*>(h + (long long)s * F1 + foff);
        acc.x += w * vv.x; acc.y += w * vv.y; acc.z += w * vv.z; acc.w += w * vv.w;
    }

    // combine edge parities: lane L <-> L^8 pairs (q0<->q1, q2<->q3)
    acc.x += __shfl_xor_sync(0xffffffffu, acc.x, 8);
    acc.y += __shfl_xor_sync(0xffffffffu, acc.y, 8);
    acc.z += __shfl_xor_sync(0xffffffffu, acc.z, 8);
    acc.w += __shfl_xor_sync(0xffffffffu, acc.w, 8);
    if (e_par == 0) {                     // q0 writes half 0, q2 writes half 1
        acc.x *= div; acc.y *= div; acc.z *= div; acc.w *= div;
        *reinterpret_cast<float4*>(g + (long long)v * F1 + foff) = acc;
    }
}

// ---------------- prop32: round-11 4-stream version -------------------------
__global__ void __launch_bounds__(256)
prop32_kernel(const float* __restrict__ h, float* __restrict__ g, int n)
{
    const int v = (blockIdx.x * blockDim.x + threadIdx.x) >> 5;
    if (v >= n) return;
    const int lane = threadIdx.x & 31;
    const int q  = lane >> 3;
    const int fl = lane & 7;
    const int r1 = min(g_cnt[v], PAD);
    const float div = g_dinv[v];
    const int* __restrict__ row = g_ell + (long long)v * PAD;

    float4 acc = make_float4(0.f, 0.f, 0.f, 0.f);
    if (q == 0) {
        acc = *reinterpret_cast<const float4*>(h + (long long)v * F2 + fl * 4);
        acc.x *= div; acc.y *= div; acc.z *= div; acc.w *= div;
    }

    int j = q;
    for (; j + 12 < r1; j += 16) {
        int s0 = row[j], s1 = row[j + 4], s2 = row[j + 8], s3 = row[j + 12];
        float w0 = g_dinv[s0], w1 = g_dinv[s1], w2 = g_dinv[s2], w3 = g_dinv[s3];
        float4 v0 = *reinterpret_cast<const float4*>(h + (long long)s0 * F2 + fl * 4);
        float4 v1 = *reinterpret_cast<const float4*>(h + (long long)s1 * F2 + fl * 4);
        float4 v2 = *reinterpret_cast<const float4*>(h + (long long)s2 * F2 + fl * 4);
        float4 v3 = *reinterpret_cast<const float4*>(h + (long long)s3 * F2 + fl * 4);
        acc.x += w0 * v0.x; acc.y += w0 * v0.y; acc.z += w0 * v0.z; acc.w += w0 * v0.w;
        acc.x += w1 * v1.x; acc.y += w1 * v1.y; acc.z += w1 * v1.z; acc.w += w1 * v1.w;
        acc.x += w2 * v2.x; acc.y += w2 * v2.y; acc.z += w2 * v2.z; acc.w += w2 * v2.w;
        acc.x += w3 * v3.x; acc.y += w3 * v3.y; acc.z += w3 * v3.z; acc.w += w3 * v3.w;
    }
    for (; j < r1; j += 4) {
        int s = row[j];
        float w = g_dinv[s];
        float4 vv = *reinterpret_cast<const float4*>(h + (long long)s * F2 + fl * 4);
        acc.x += w * vv.x; acc.y += w * vv.y; acc.z += w * vv.z; acc.w += w * vv.w;
    }

#pragma unroll
    for (int o = 8; o <= 16; o <<= 1) {
        acc.x += __shfl_xor_sync(0xffffffffu, acc.x, o);
        acc.y += __shfl_xor_sync(0xffffffffu, acc.y, o);
        acc.z += __shfl_xor_sync(0xffffffffu, acc.z, o);
        acc.w += __shfl_xor_sync(0xffffffffu, acc.w, o);
    }
    if (q == 0) {
        acc.x *= div; acc.y *= div; acc.z *= div; acc.w *= div;
        *reinterpret_cast<float4*>(g + (long long)v * F2 + fl * 4) = acc;
    }
}

// ---------------- launcher (round-11 forked-stream structure) ---------------
extern "C" void kernel_launch(void* const* d_in, const int* in_sizes, int n_in,
                              void* d_out, int out_size)
{
    const float* x  = (const float*)d_in[0];
    const int*   ei = (const int*)  d_in[1];
    const float* W1 = (const float*)d_in[2];
    const float* b1 = (const float*)d_in[3];
    const float* W2 = (const float*)d_in[4];
    const float* b2 = (const float*)d_in[5];
    const float* Wl = (const float*)d_in[6];
    const float* bl = (const float*)d_in[7];
    float* out = (float*)d_out;

    const int n = in_sizes[0] / DIN;
    const int E = in_sizes[1] / 2;

    void *ph1, *pa1, *ph2, *pa2;
    cudaGetSymbolAddress(&ph1, g_h1);
    cudaGetSymbolAddress(&pa1, g_a1);
    cudaGetSymbolAddress(&ph2, g_h2);
    cudaGetSymbolAddress(&pa2, g_a2);
    float* h1 = (float*)ph1; float* a1 = (float*)pa1;
    float* h2 = (float*)ph2; float* a2 = (float*)pa2;

    const int nblk = (n + 127) / 128;    // TM=128
    const int pblk = (n * 32 + 255) / 256;

    cudaStream_t s2;
    cudaStreamCreateWithFlags(&s2, cudaStreamNonBlocking);
    cudaEvent_t evFork, evJoin;
    cudaEventCreateWithFlags(&evFork, cudaEventDisableTiming);
    cudaEventCreateWithFlags(&evJoin, cudaEventDisableTiming);

    // fork: ELL build on s2, concurrent with gemm1 on the main stream
    cudaEventRecord(evFork, 0);
    cudaStreamWaitEvent(s2, evFork, 0);

    detect_kernel<<<1, 256, 0, s2>>>(ei, E);
    scatter_count_kernel<<<(E + 255) / 256, 256, 0, s2>>>(ei, E);
    dinv_kernel<<<(n + 255) / 256, 256, 0, s2>>>(n);
    cudaEventRecord(evJoin, s2);

    // main stream: layer-1 GEMM overlaps ELL build
    gemm_rt2<DIN, F1, 64, false, false, false>
        <<<dim3(nblk, 1), 128>>>(x, W1, nullptr, nullptr, h1, n);

    cudaStreamWaitEvent(0, evJoin, 0);

    prop64_kernel<<<pblk, 256>>>(h1, a1, n);
    gemm_rt2<F1, F2, 32, true, false, false>
        <<<dim3(nblk, 1), 64>>>(a1, W2, b1, nullptr, h2, n);
    prop32_kernel<<<pblk, 256>>>(h2, a2, n);
    // gemm3 also re-zeroes g_cnt for the next replay (ZCNT=true)
    gemm_rt2<F2, DOUT, 64, true, true, true>
        <<<dim3(nblk, 2), 128>>>(a2, Wl, b2, bl, out, n);

    cudaEventDestroy(evFork);
    cudaEventDestroy(evJoin);
    cudaStreamDestroy(s2);
}